// round 14
// baseline (speedup 1.0000x reference)
#include <cuda_runtime.h>
#include <cuda_fp16.h>
#include <math.h>
#include <float.h>
#include <stdint.h>

// ============================================================================
// DeepSeekV3 MoE Gate (sm_103a; PTX target compute_103 -> no tcgen05).
// R14: ONE persistent kernel, 148 CTAs (all co-resident), 3 phases:
//   phase 0: split W (x64 prescale) -> fp16 hi/mid   (grid-stride)
//   phase 1: GEMM work loop over 256 items (128 big-K + 128 small-K tiles,
//            atomic-counter work stealing; mainloop byte-identical to R12)
//   phase 2: grouped top-k (REDUX, 56 tokens/CTA)
// Software grid barrier (spin on generation flag; safe: 1 CTA/SM co-resident).
// Output (float32): [ T*8 indices (as float) | T*8 weights ]
// ============================================================================

#define N_EXPERTS 256
#define TOPK_GRP  4
#define TOP_K     8
#define SCALE     2.5f
#define H_DIM     7168
#define MAX_T     8192
#define W_PRESCALE   64.0f
#define W_POSTSCALE  0.015625f   // 1/64
#define GRID_SIZE 148

__device__ float g_logits [MAX_T * N_EXPERTS];                // big partials
__device__ float g_logits2[MAX_T * N_EXPERTS];                // small partials
__device__ __align__(16) __half g_wh[N_EXPERTS * H_DIM];      // fp16(64*w)
__device__ __align__(16) __half g_wm[N_EXPERTS * H_DIM];      // fp16(64*w - hi)

// persistent-kernel coordination (all statically zero-initialized)
__device__ int g_flag   = 0;   // generation flag (monotone across replays)
__device__ int g_arrive = 0;   // barrier arrival counter (reset each use)
__device__ int g_work   = 0;   // GEMM work-item counter (reset each launch)

// ---------------------------------------------------------------------------
// helpers
// ---------------------------------------------------------------------------
__device__ __forceinline__ uint32_t smem_to_u32(const void* p) {
    uint32_t a;
    asm("{ .reg .u64 t; cvta.to.shared.u64 t, %1; cvt.u32.u64 %0, t; }"
        : "=r"(a) : "l"(p));
    return a;
}
__device__ __forceinline__ void cp16(uint32_t dst, const void* src) {
    asm volatile("cp.async.cg.shared.global [%0], [%1], 16;" :: "r"(dst), "l"(src));
}
#define CP_COMMIT() asm volatile("cp.async.commit_group;" ::: "memory")
#define CP_WAIT1()  asm volatile("cp.async.wait_group 1;" ::: "memory")

__device__ __forceinline__ void ldmatrix_x4(uint32_t* r, uint32_t addr) {
    asm volatile("ldmatrix.sync.aligned.m8n8.x4.shared.b16 {%0,%1,%2,%3}, [%4];"
                 : "=r"(r[0]), "=r"(r[1]), "=r"(r[2]), "=r"(r[3]) : "r"(addr));
}
__device__ __forceinline__ void mma_fp16(float* d, const uint32_t* a,
                                         uint32_t b0, uint32_t b1) {
    asm volatile(
        "mma.sync.aligned.m16n8k16.row.col.f32.f16.f16.f32 "
        "{%0,%1,%2,%3}, {%4,%5,%6,%7}, {%8,%9}, {%0,%1,%2,%3};"
        : "+f"(d[0]), "+f"(d[1]), "+f"(d[2]), "+f"(d[3])
        : "r"(a[0]), "r"(a[1]), "r"(a[2]), "r"(a[3]), "r"(b0), "r"(b1));
}

// split a float2 into 2 packed fp16x2 (hi, mid); low 16 bits = f.x
__device__ __forceinline__ void split2(float2 f, uint32_t& h, uint32_t& m) {
    __half2 hh = __floats2half2_rn(f.x, f.y);
    h = *reinterpret_cast<uint32_t*>(&hh);
    float2 hf = __half22float2(hh);
    __half2 mm2 = __floats2half2_rn(f.x - hf.x, f.y - hf.y);
    m = *reinterpret_cast<uint32_t*>(&mm2);
}

// monotone float <-> unsigned-comparable key (finite inputs map to key > 0)
__device__ __forceinline__ unsigned f2ord(float f) {
    unsigned u = __float_as_uint(f);
    return u ^ ((((int)u) >> 31) | 0x80000000u);
}
__device__ __forceinline__ float ord2f(unsigned k) {
    unsigned u = (k & 0x80000000u) ? (k ^ 0x80000000u) : ~k;
    return __uint_as_float(u);
}

// software grid barrier: all 148 CTAs co-resident (1 CTA/SM) -> spin is safe.
// Release: syncthreads (CTA-scope) -> thread0 fence.gpu -> flag store.
// Acquire: spin on flag -> fence.gpu -> syncthreads.
__device__ __forceinline__ void grid_barrier(int target, bool reset_work) {
    __syncthreads();
    if (threadIdx.x == 0) {
        __threadfence();
        int ret = atomicAdd(&g_arrive, 1);
        if (ret == GRID_SIZE - 1) {
            g_arrive = 0;                 // all arrivals done; safe to reset
            if (reset_work) g_work = 0;   // for next replay
            __threadfence();
            *(volatile int*)&g_flag = target;
        } else {
            while (*(volatile int*)&g_flag - target < 0) __nanosleep(64);
            __threadfence();
        }
    }
    __syncthreads();
}

// ---------------------------------------------------------------------------
// GEMM geometry (PROVEN R12 split-K layout — do not modify)
// ---------------------------------------------------------------------------
#define BM        128
#define BN        128
#define BK        64
#define NCHUNK    (H_DIM / BK)          // 112
#define BIGC      100                   // big segment: chunks 0..99 (K=6400)
#define FLUSH_MASK 3                    // flush every 4 local chunks (K=256)
#define A_ROWB    288                   // 72 floats
#define A_BYTES   (128 * A_ROWB)        // 36864
#define B_ROWB    144
#define B_SPLIT_B (128 * B_ROWB)        // 18432
#define STAGE_B   (A_BYTES + 2 * B_SPLIT_B)  // 73728
#define GEMM_SMEM (3 * STAGE_B)              // 221184

__device__ __forceinline__ void load_stage(const float* __restrict__ x,
                                           int row0, int e0, int k0,
                                           uint32_t stage_base, int tid)
{
    // A: 128 rows x 64 fp32 (256B payload/row, stride 288B): 2048 cp16
#pragma unroll
    for (int l = 0; l < 8; l++) {
        int q = tid + 256 * l;             // 0..2047
        int row = q >> 4, seg = q & 15;
        const float* src = x + (size_t)(row0 + row) * H_DIM + k0 + seg * 4;
        cp16(stage_base + row * A_ROWB + seg * 16, src);
    }
    // B: 2 splits x 128 rows x 64 fp16 (128B payload/row, stride 144B): 2048 cp16
#pragma unroll
    for (int l = 0; l < 8; l++) {
        int q = tid + 256 * l;             // 0..2047
        int s = q >> 10;                   // split
        int r = q & 1023;
        int row = r >> 3, seg = r & 7;
        const __half* wp = s ? g_wm : g_wh;
        const __half* src = wp + (size_t)(e0 + row) * H_DIM + k0 + seg * 8;
        cp16(stage_base + A_BYTES + s * B_SPLIT_B + row * B_ROWB + seg * 16, src);
    }
}

// ---------------------------------------------------------------------------
// The persistent kernel
// ---------------------------------------------------------------------------
__global__ __launch_bounds__(256, 1)
void moe_persistent(const float* __restrict__ x,
                    const float* __restrict__ w,
                    const float* __restrict__ bias,
                    float* __restrict__ out, int T)
{
    extern __shared__ char smem[];
    __shared__ int s_item;
    const uint32_t sbase = smem_to_u32(smem);
    const int tid  = threadIdx.x;
    const int lane = tid & 31;
    const int wid  = tid >> 5;
    const int wm   = wid & 3;              // warp row (m)
    const int wn   = wid >> 2;             // warp col (n)

    int f0 = 0;
    if (tid == 0) f0 = *(volatile int*)&g_flag;   // stable between replays

    // ============ phase 0: split prescaled W into fp16 hi/mid ============
    {
        const int n4 = N_EXPERTS * H_DIM / 4;
        for (int i = blockIdx.x * 256 + tid; i < n4; i += GRID_SIZE * 256) {
            float4 v = reinterpret_cast<const float4*>(w)[i];
            uint32_t h0, m0, h1, m1;
            split2(make_float2(v.x * W_PRESCALE, v.y * W_PRESCALE), h0, m0);
            split2(make_float2(v.z * W_PRESCALE, v.w * W_PRESCALE), h1, m1);
            reinterpret_cast<uint2*>(g_wh)[i] = make_uint2(h0, h1);
            reinterpret_cast<uint2*>(g_wm)[i] = make_uint2(m0, m1);
        }
    }
    if (tid == 0) s_item = f0;             // broadcast f0 via smem
    grid_barrier(f0 + 1, false);           // (only thread 0's f0 is used inside)
    f0 = s_item;                           // now all threads hold f0 (post-barrier)

    // ============ phase 1: GEMM work loop (256 items) ============
    const int c2 = (lane & 3) * 2;         // k-pair base within 8
    for (;;) {
        __syncthreads();                   // item end: protect smem slots + s_item
        if (tid == 0) s_item = atomicAdd(&g_work, 1);
        __syncthreads();
        const int item = s_item;
        if (item >= 256) break;

        const bool big = item < 128;
        const int tile = big ? item : item - 128;
        const int row0 = (tile >> 1) * BM;
        const int e0   = (tile & 1) * BN;
        const int c0   = big ? 0 : BIGC;
        const int cn   = big ? BIGC : NCHUNK;
        float* dst = big ? g_logits : g_logits2;

        float acc[2][8][4];
        float master[2][8][4];
#pragma unroll
        for (int mt = 0; mt < 2; mt++)
#pragma unroll
            for (int nt = 0; nt < 8; nt++)
#pragma unroll
                for (int q = 0; q < 4; q++) { acc[mt][nt][q] = 0.0f; master[mt][nt][q] = 0.0f; }

        // prologue: stages c0, c0+1
        load_stage(x, row0, e0, c0 * BK,       sbase + 0 * STAGE_B, tid); CP_COMMIT();
        load_stage(x, row0, e0, (c0 + 1) * BK, sbase + 1 * STAGE_B, tid); CP_COMMIT();

        for (int lc = 0; lc < cn - c0; ++lc) {
            const int c = c0 + lc;
            CP_WAIT1();
            __syncthreads();

            if (c + 2 < cn)
                load_stage(x, row0, e0, (c + 2) * BK, sbase + ((lc + 2) % 3) * STAGE_B, tid);
            CP_COMMIT();

            const int slot = lc % 3;
            const char* As = smem + slot * STAGE_B;
            const uint32_t Bs = sbase + slot * STAGE_B + A_BYTES;

#pragma unroll
            for (int kk = 0; kk < 4; kk++) {       // four k16 steps per BK=64
                uint32_t ah[2][4], am[2][4];
#pragma unroll
                for (int mt = 0; mt < 2; mt++) {
                    int brow = wm * 32 + mt * 16 + (lane >> 2);
#pragma unroll
                    for (int q = 0; q < 4; q++) {
                        int r   = brow + (q & 1) * 8;
                        int col = kk * 16 + c2 + (q >> 1) * 8;
                        float2 f = *reinterpret_cast<const float2*>(As + r * A_ROWB + col * 4);
                        split2(f, ah[mt][q], am[mt][q]);
                    }
                }
                // 3 passes: s=0 -> ah*bh + am*bh ; s=1 -> ah*bm
#pragma unroll
                for (int s = 0; s < 2; s++) {
                    uint32_t b[4][4];
#pragma unroll
                    for (int p = 0; p < 4; p++) {
                        int row = wn * 64 + p * 16 + (lane & 7) + ((lane >> 4) & 1) * 8;
                        uint32_t addr = Bs + s * B_SPLIT_B + row * B_ROWB
                                      + kk * 32 + ((lane >> 3) & 1) * 16;
                        ldmatrix_x4(b[p], addr);
                    }
#pragma unroll
                    for (int mt = 0; mt < 2; mt++)
#pragma unroll
                        for (int nt = 0; nt < 8; nt++) {
                            int p = nt >> 1, o = (nt & 1) * 2;
                            mma_fp16(acc[mt][nt], ah[mt], b[p][o], b[p][o + 1]);
                        }
                    if (s == 0) {
#pragma unroll
                        for (int mt = 0; mt < 2; mt++)
#pragma unroll
                            for (int nt = 0; nt < 8; nt++) {
                                int p = nt >> 1, o = (nt & 1) * 2;
                                mma_fp16(acc[mt][nt], am[mt], b[p][o], b[p][o + 1]);
                            }
                    }
                }
            }

            // RN flush: keep tensor-core accumulation chains short
            if ((lc & FLUSH_MASK) == FLUSH_MASK) {
#pragma unroll
                for (int mt = 0; mt < 2; mt++)
#pragma unroll
                    for (int nt = 0; nt < 8; nt++)
#pragma unroll
                        for (int q = 0; q < 4; q++) {
                            master[mt][nt][q] += acc[mt][nt][q];
                            acc[mt][nt][q] = 0.0f;
                        }
            }
        }

        // fold residual chunks
#pragma unroll
        for (int mt = 0; mt < 2; mt++)
#pragma unroll
            for (int nt = 0; nt < 8; nt++)
#pragma unroll
                for (int q = 0; q < 4; q++) master[mt][nt][q] += acc[mt][nt][q];

        // epilogue: write partial logits (undo W prescale)
#pragma unroll
        for (int mt = 0; mt < 2; mt++) {
            int row = row0 + wm * 32 + mt * 16 + (lane >> 2);
#pragma unroll
            for (int nt = 0; nt < 8; nt++) {
                int col = e0 + wn * 64 + nt * 8 + c2;
                *reinterpret_cast<float2*>(&dst[(size_t)row * N_EXPERTS + col]) =
                    make_float2(master[mt][nt][0] * W_POSTSCALE,
                                master[mt][nt][1] * W_POSTSCALE);
                *reinterpret_cast<float2*>(&dst[(size_t)(row + 8) * N_EXPERTS + col]) =
                    make_float2(master[mt][nt][2] * W_POSTSCALE,
                                master[mt][nt][3] * W_POSTSCALE);
            }
        }
    }

    grid_barrier(f0 + 2, true);            // all partial logits visible; reset work ctr

    // ============ phase 2: grouped top-k (56 tokens/CTA, 7 per warp) ============
    const unsigned FULL = 0xFFFFFFFFu;
    const int tbase = blockIdx.x * 56 + wid * 7;
    for (int ti = 0; ti < 7; ti++) {
        const int t = tbase + ti;
        if (t >= T) break;

        const float* lg  = &g_logits [(size_t)t * N_EXPERTS];
        const float* lg2 = &g_logits2[(size_t)t * N_EXPERTS];

        float s[8];
        unsigned k[8];
#pragma unroll
        for (int j = 0; j < 8; j++) {
            int e = j * 32 + lane;
            float logit = lg[e] + lg2[e];  // fixed-order partial sum
            float sv = 1.0f / (1.0f + __expf(-logit));
            s[j] = sv;
            k[j] = f2ord(sv + bias[e]);
        }

        // per-group top-2 sum via REDUX (sum is tie-insensitive)
        float gs[8];
#pragma unroll
        for (int g = 0; g < 8; g++) {
            unsigned m1 = __reduce_max_sync(FULL, k[g]);
            unsigned bal = __ballot_sync(FULL, k[g] == m1);
            int leader = __ffs(bal) - 1;
            unsigned k2 = (lane == leader) ? 0u : k[g];
            unsigned m2 = __reduce_max_sync(FULL, k2);
            gs[g] = ord2f(m1) + ord2f(m2);
        }

        unsigned gmask = 0;
#pragma unroll
        for (int r = 0; r < TOPK_GRP; r++) {
            float best = -FLT_MAX; int bg = 0;
#pragma unroll
            for (int g = 0; g < 8; g++) {
                bool taken = (gmask >> g) & 1u;
                if (!taken && gs[g] > best) { best = gs[g]; bg = g; }
            }
            gmask |= (1u << bg);
        }

        unsigned kv[8];
#pragma unroll
        for (int j = 0; j < 8; j++)
            kv[j] = ((gmask >> j) & 1u) ? k[j] : 0u;

        float wts[TOP_K];
        int   idxs[TOP_K];
        float wsum = 0.0f;
#pragma unroll
        for (int r = 0; r < TOP_K; r++) {
            unsigned kb = kv[0];
#pragma unroll
            for (int j = 1; j < 8; j++) kb = kb > kv[j] ? kb : kv[j];
            unsigned m = __reduce_max_sync(FULL, kb);
            int myidx = 0x7FFFFFFF;
#pragma unroll
            for (int j = 7; j >= 0; j--)
                if (kv[j] == m) myidx = j * 32 + lane;
            int widx = __reduce_min_sync(FULL, myidx);

            int wl = widx & 31;
            int wj = widx >> 5;
            float sv_local = 0.0f;
#pragma unroll
            for (int j = 0; j < 8; j++) if (j == wj) sv_local = s[j];
            float sv = __shfl_sync(FULL, sv_local, wl);

            idxs[r] = widx;
            wts[r]  = sv;
            wsum   += sv;

            if (lane == wl) {
#pragma unroll
                for (int j = 0; j < 8; j++) if (j == wj) kv[j] = 0u;
            }
        }

        if (lane == 0) {
            float inv = SCALE / wsum;
            size_t half = (size_t)T * TOP_K;
#pragma unroll
            for (int r = 0; r < TOP_K; r++) {
                out[(size_t)t * TOP_K + r]        = (float)idxs[r];
                out[half + (size_t)t * TOP_K + r] = wts[r] * inv;
            }
        }
    }
}

// ---------------------------------------------------------------------------
extern "C" void kernel_launch(void* const* d_in, const int* in_sizes, int n_in,
                              void* d_out, int out_size)
{
    const float* x    = (const float*)d_in[0];   // [B,S,H] fp32
    const float* w    = (const float*)d_in[1];   // [E,H]   fp32
    const float* bias = (const float*)d_in[2];   // [E]     fp32
    float* out = (float*)d_out;

    const int E = in_sizes[2];                   // 256
    const int H = in_sizes[1] / E;               // 7168
    const int T = in_sizes[0] / H;               // 8192
    (void)E; (void)H;

    cudaFuncSetAttribute(moe_persistent,
                         cudaFuncAttributeMaxDynamicSharedMemorySize, GEMM_SMEM);
    moe_persistent<<<GRID_SIZE, 256, GEMM_SMEM>>>(x, w, bias, out, T);
}

// round 15
// speedup vs baseline: 1.1854x; 1.1854x over previous
#include <cuda_runtime.h>
#include <cuda_fp16.h>
#include <math.h>
#include <float.h>
#include <stdint.h>

// ============================================================================
// DeepSeekV3 MoE Gate (sm_103a; PTX target compute_103 -> no tcgen05).
// GEMM via mma.sync.m16n8k16 fp16, fp16x2 split, 3 passes (hh, hm, mh),
// W prescaled x64 (single fp32 accumulator), periodic RN master flush.
// R12 split-K layout: 128 big tiles (K-chunks 0..99) + 128 small tiles
// (chunks 100..111) backfilling the 20 otherwise-idle SMs.
// R15: revert persistent experiment (reg-spill regression); R13 structure
// restored; topk now 2 tokens/warp for REDUX-chain ILP.
// Output (float32): [ T*8 indices (as float) | T*8 weights ]
// ============================================================================

#define N_EXPERTS 256
#define TOPK_GRP  4
#define TOP_K     8
#define SCALE     2.5f
#define H_DIM     7168
#define MAX_T     8192
#define W_PRESCALE   64.0f
#define W_POSTSCALE  0.015625f   // 1/64

__device__ float g_logits [MAX_T * N_EXPERTS];                // big partials
__device__ float g_logits2[MAX_T * N_EXPERTS];                // small partials
__device__ __align__(16) __half g_wh[N_EXPERTS * H_DIM];      // fp16(64*w)
__device__ __align__(16) __half g_wm[N_EXPERTS * H_DIM];      // fp16(64*w - hi)

// ---------------------------------------------------------------------------
// helpers
// ---------------------------------------------------------------------------
__device__ __forceinline__ uint32_t smem_to_u32(const void* p) {
    uint32_t a;
    asm("{ .reg .u64 t; cvta.to.shared.u64 t, %1; cvt.u32.u64 %0, t; }"
        : "=r"(a) : "l"(p));
    return a;
}
__device__ __forceinline__ void cp16(uint32_t dst, const void* src) {
    asm volatile("cp.async.cg.shared.global [%0], [%1], 16;" :: "r"(dst), "l"(src));
}
#define CP_COMMIT() asm volatile("cp.async.commit_group;" ::: "memory")
#define CP_WAIT1()  asm volatile("cp.async.wait_group 1;" ::: "memory")

__device__ __forceinline__ void ldmatrix_x4(uint32_t* r, uint32_t addr) {
    asm volatile("ldmatrix.sync.aligned.m8n8.x4.shared.b16 {%0,%1,%2,%3}, [%4];"
                 : "=r"(r[0]), "=r"(r[1]), "=r"(r[2]), "=r"(r[3]) : "r"(addr));
}
__device__ __forceinline__ void mma_fp16(float* d, const uint32_t* a,
                                         uint32_t b0, uint32_t b1) {
    asm volatile(
        "mma.sync.aligned.m16n8k16.row.col.f32.f16.f16.f32 "
        "{%0,%1,%2,%3}, {%4,%5,%6,%7}, {%8,%9}, {%0,%1,%2,%3};"
        : "+f"(d[0]), "+f"(d[1]), "+f"(d[2]), "+f"(d[3])
        : "r"(a[0]), "r"(a[1]), "r"(a[2]), "r"(a[3]), "r"(b0), "r"(b1));
}

// split a float2 into 2 packed fp16x2 (hi, mid); low 16 bits = f.x
__device__ __forceinline__ void split2(float2 f, uint32_t& h, uint32_t& m) {
    __half2 hh = __floats2half2_rn(f.x, f.y);
    h = *reinterpret_cast<uint32_t*>(&hh);
    float2 hf = __half22float2(hh);
    __half2 mm2 = __floats2half2_rn(f.x - hf.x, f.y - hf.y);
    m = *reinterpret_cast<uint32_t*>(&mm2);
}

// monotone float <-> unsigned-comparable key (finite inputs map to key > 0)
__device__ __forceinline__ unsigned f2ord(float f) {
    unsigned u = __float_as_uint(f);
    return u ^ ((((int)u) >> 31) | 0x80000000u);
}
__device__ __forceinline__ float ord2f(unsigned k) {
    unsigned u = (k & 0x80000000u) ? (k ^ 0x80000000u) : ~k;
    return __uint_as_float(u);
}

// ---------------------------------------------------------------------------
// Kernel 0: split prescaled fp32 weights -> 2 fp16 tensors (4 float4/thread)
// ---------------------------------------------------------------------------
__global__ __launch_bounds__(256)
void split_w_kernel(const float* __restrict__ w)
{
    const int n4 = N_EXPERTS * H_DIM / 4;
    int base = blockIdx.x * 1024 + threadIdx.x;
    float4 v[4];
    int idx[4];
#pragma unroll
    for (int r = 0; r < 4; r++) {
        idx[r] = base + r * 256;
        if (idx[r] < n4) v[r] = reinterpret_cast<const float4*>(w)[idx[r]];
    }
#pragma unroll
    for (int r = 0; r < 4; r++) {
        if (idx[r] >= n4) break;
        uint32_t h0, m0, h1, m1;
        split2(make_float2(v[r].x * W_PRESCALE, v[r].y * W_PRESCALE), h0, m0);
        split2(make_float2(v[r].z * W_PRESCALE, v[r].w * W_PRESCALE), h1, m1);
        reinterpret_cast<uint2*>(g_wh)[idx[r]] = make_uint2(h0, h1);
        reinterpret_cast<uint2*>(g_wm)[idx[r]] = make_uint2(m0, m1);
    }
}

// ---------------------------------------------------------------------------
// Kernel 1: GEMM via mma.sync fp16x2, 3 passes, single accumulator + RN flush.
// CTA tile: 128 tokens x 128 experts, split in K:
//   bid 0..127  : big   segment, chunks [0, BIGC)
//   bid 128..255: small segment, chunks [BIGC, NCHUNK)
// BK=64. 3-stage cp.async pipeline. 1 CTA/SM. (PROVEN — do not modify.)
// ---------------------------------------------------------------------------
#define BM        128
#define BN        128
#define BK        64
#define NCHUNK    (H_DIM / BK)          // 112
#define BIGC      100                   // big segment: chunks 0..99 (K=6400)
#define FLUSH_MASK 3                    // flush every 4 local chunks (K=256)
#define A_ROWB    288                   // 72 floats
#define A_BYTES   (128 * A_ROWB)        // 36864
#define B_ROWB    144
#define B_SPLIT_B (128 * B_ROWB)        // 18432
#define STAGE_B   (A_BYTES + 2 * B_SPLIT_B)  // 73728
#define GEMM_SMEM (3 * STAGE_B)              // 221184

__device__ __forceinline__ void load_stage(const float* __restrict__ x,
                                           int row0, int e0, int k0,
                                           uint32_t stage_base, int tid)
{
    // A: 128 rows x 64 fp32 (256B payload/row, stride 288B): 2048 cp16
#pragma unroll
    for (int l = 0; l < 8; l++) {
        int q = tid + 256 * l;             // 0..2047
        int row = q >> 4, seg = q & 15;
        const float* src = x + (size_t)(row0 + row) * H_DIM + k0 + seg * 4;
        cp16(stage_base + row * A_ROWB + seg * 16, src);
    }
    // B: 2 splits x 128 rows x 64 fp16 (128B payload/row, stride 144B): 2048 cp16
#pragma unroll
    for (int l = 0; l < 8; l++) {
        int q = tid + 256 * l;             // 0..2047
        int s = q >> 10;                   // split
        int r = q & 1023;
        int row = r >> 3, seg = r & 7;
        const __half* wp = s ? g_wm : g_wh;
        const __half* src = wp + (size_t)(e0 + row) * H_DIM + k0 + seg * 8;
        cp16(stage_base + A_BYTES + s * B_SPLIT_B + row * B_ROWB + seg * 16, src);
    }
}

__global__ __launch_bounds__(256, 1)
void moe_gemm_mma(const float* __restrict__ x)
{
    extern __shared__ char smem[];
    const uint32_t sbase = smem_to_u32(smem);
    const int tid  = threadIdx.x;
    const int lane = tid & 31;
    const int wid  = tid >> 5;
    const int wm   = wid & 3;              // warp row (m)
    const int wn   = wid >> 2;             // warp col (n)

    const int bid  = blockIdx.x;
    const bool big = bid < 128;
    const int tile = big ? bid : bid - 128;
    const int row0 = (tile >> 1) * BM;
    const int e0   = (tile & 1) * BN;
    const int c0   = big ? 0 : BIGC;       // first chunk (inclusive)
    const int cn   = big ? BIGC : NCHUNK;  // last chunk (exclusive)
    float* dst = big ? g_logits : g_logits2;

    float acc[2][8][4];                    // short-chain accumulators
    float master[2][8][4];                 // RN-summed masters
#pragma unroll
    for (int mt = 0; mt < 2; mt++)
#pragma unroll
        for (int nt = 0; nt < 8; nt++)
#pragma unroll
            for (int q = 0; q < 4; q++) { acc[mt][nt][q] = 0.0f; master[mt][nt][q] = 0.0f; }

    // prologue: stages c0, c0+1
    load_stage(x, row0, e0, c0 * BK,       sbase + 0 * STAGE_B, tid); CP_COMMIT();
    load_stage(x, row0, e0, (c0 + 1) * BK, sbase + 1 * STAGE_B, tid); CP_COMMIT();

    const int c2 = (lane & 3) * 2;         // k-pair base within 8

    for (int lc = 0; lc < cn - c0; ++lc) { // local chunk index
        const int c = c0 + lc;
        CP_WAIT1();
        __syncthreads();

        if (c + 2 < cn)
            load_stage(x, row0, e0, (c + 2) * BK, sbase + ((lc + 2) % 3) * STAGE_B, tid);
        CP_COMMIT();

        const int slot = lc % 3;
        const char* As = smem + slot * STAGE_B;
        const uint32_t Bs = sbase + slot * STAGE_B + A_BYTES;

#pragma unroll
        for (int kk = 0; kk < 4; kk++) {           // four k16 steps per BK=64
            // ---- A fragments: load fp32 pairs, split to fp16x2 ----
            uint32_t ah[2][4], am[2][4];
#pragma unroll
            for (int mt = 0; mt < 2; mt++) {
                int brow = wm * 32 + mt * 16 + (lane >> 2);
#pragma unroll
                for (int q = 0; q < 4; q++) {
                    int r   = brow + (q & 1) * 8;
                    int col = kk * 16 + c2 + (q >> 1) * 8;
                    float2 f = *reinterpret_cast<const float2*>(As + r * A_ROWB + col * 4);
                    split2(f, ah[mt][q], am[mt][q]);
                }
            }
            // ---- 3 passes: s=0 -> ah*bh + am*bh ; s=1 -> ah*bm ----
#pragma unroll
            for (int s = 0; s < 2; s++) {
                uint32_t b[4][4];
#pragma unroll
                for (int p = 0; p < 4; p++) {
                    int row = wn * 64 + p * 16 + (lane & 7) + ((lane >> 4) & 1) * 8;
                    uint32_t addr = Bs + s * B_SPLIT_B + row * B_ROWB
                                  + kk * 32 + ((lane >> 3) & 1) * 16;
                    ldmatrix_x4(b[p], addr);
                }
#pragma unroll
                for (int mt = 0; mt < 2; mt++)
#pragma unroll
                    for (int nt = 0; nt < 8; nt++) {
                        int p = nt >> 1, o = (nt & 1) * 2;
                        mma_fp16(acc[mt][nt], ah[mt], b[p][o], b[p][o + 1]);
                    }
                if (s == 0) {
#pragma unroll
                    for (int mt = 0; mt < 2; mt++)
#pragma unroll
                        for (int nt = 0; nt < 8; nt++) {
                            int p = nt >> 1, o = (nt & 1) * 2;
                            mma_fp16(acc[mt][nt], am[mt], b[p][o], b[p][o + 1]);
                        }
                }
            }
        }

        // ---- RN flush: keep tensor-core accumulation chains short ----
        if ((lc & FLUSH_MASK) == FLUSH_MASK) {
#pragma unroll
            for (int mt = 0; mt < 2; mt++)
#pragma unroll
                for (int nt = 0; nt < 8; nt++)
#pragma unroll
                    for (int q = 0; q < 4; q++) {
                        master[mt][nt][q] += acc[mt][nt][q];
                        acc[mt][nt][q] = 0.0f;
                    }
        }
    }

    // fold residual chunks (segment length may not be multiple of 4)
#pragma unroll
    for (int mt = 0; mt < 2; mt++)
#pragma unroll
        for (int nt = 0; nt < 8; nt++)
#pragma unroll
            for (int q = 0; q < 4; q++) master[mt][nt][q] += acc[mt][nt][q];

    // epilogue: write partial logits (undo W prescale)
#pragma unroll
    for (int mt = 0; mt < 2; mt++) {
        int row = row0 + wm * 32 + mt * 16 + (lane >> 2);
#pragma unroll
        for (int nt = 0; nt < 8; nt++) {
            int col = e0 + wn * 64 + nt * 8 + c2;
            *reinterpret_cast<float2*>(&dst[(size_t)row * N_EXPERTS + col]) =
                make_float2(master[mt][nt][0] * W_POSTSCALE,
                            master[mt][nt][1] * W_POSTSCALE);
            *reinterpret_cast<float2*>(&dst[(size_t)(row + 8) * N_EXPERTS + col]) =
                make_float2(master[mt][nt][2] * W_POSTSCALE,
                            master[mt][nt][3] * W_POSTSCALE);
        }
    }
}

// ---------------------------------------------------------------------------
// Kernel 2: per-token grouped top-k. 2 tokens per warp (REDUX-chain ILP).
// Tie semantics preserved exactly: value desc, tie -> lowest expert index.
// ---------------------------------------------------------------------------
__global__ __launch_bounds__(256)
void moe_topk_kernel(const float* __restrict__ bias, float* __restrict__ out, int T)
{
    const unsigned FULL = 0xFFFFFFFFu;
    const int lane   = threadIdx.x & 31;
    const int warpId = threadIdx.x >> 5;
    const int t0 = blockIdx.x * 16 + warpId * 2;

#pragma unroll
    for (int u = 0; u < 2; u++) {
        const int t = t0 + u;
        if (t >= T) break;

        const float* lg  = &g_logits [(size_t)t * N_EXPERTS];
        const float* lg2 = &g_logits2[(size_t)t * N_EXPERTS];

        float s[8];
        unsigned k[8];                         // monotone keys of sb (all > 0)
#pragma unroll
        for (int j = 0; j < 8; j++) {
            int e = j * 32 + lane;
            float logit = lg[e] + lg2[e];      // fixed-order partial sum
            float sv = 1.0f / (1.0f + __expf(-logit));
            s[j] = sv;
            k[j] = f2ord(sv + bias[e]);
        }

        // per-group top-2 sum via REDUX (sum is tie-insensitive)
        float gs[8];
#pragma unroll
        for (int g = 0; g < 8; g++) {
            unsigned m1 = __reduce_max_sync(FULL, k[g]);
            unsigned bal = __ballot_sync(FULL, k[g] == m1);
            int leader = __ffs(bal) - 1;
            unsigned k2 = (lane == leader) ? 0u : k[g];
            unsigned m2 = __reduce_max_sync(FULL, k2);
            gs[g] = ord2f(m1) + ord2f(m2);
        }

        unsigned gmask = 0;
#pragma unroll
        for (int r = 0; r < TOPK_GRP; r++) {
            float best = -FLT_MAX; int bg = 0;
#pragma unroll
            for (int g = 0; g < 8; g++) {
                bool taken = (gmask >> g) & 1u;
                if (!taken && gs[g] > best) { best = gs[g]; bg = g; }
            }
            gmask |= (1u << bg);
        }

        // candidate keys: 0 = removed/inactive (all real keys > 0)
        unsigned kv[8];
#pragma unroll
        for (int j = 0; j < 8; j++)
            kv[j] = ((gmask >> j) & 1u) ? k[j] : 0u;

        float wts[TOP_K];
        int   idxs[TOP_K];
        float wsum = 0.0f;
#pragma unroll
        for (int r = 0; r < TOP_K; r++) {
            // lane-local max key
            unsigned kb = kv[0];
#pragma unroll
            for (int j = 1; j < 8; j++) kb = kb > kv[j] ? kb : kv[j];
            // warp max key
            unsigned m = __reduce_max_sync(FULL, kb);
            // lowest expert index holding key m (descending j -> final = smallest j)
            int myidx = 0x7FFFFFFF;
#pragma unroll
            for (int j = 7; j >= 0; j--)
                if (kv[j] == m) myidx = j * 32 + lane;
            int widx = __reduce_min_sync(FULL, myidx);

            int wl = widx & 31;
            int wj = widx >> 5;
            float sv_local = 0.0f;
#pragma unroll
            for (int j = 0; j < 8; j++) if (j == wj) sv_local = s[j];
            float sv = __shfl_sync(FULL, sv_local, wl);

            idxs[r] = widx;
            wts[r]  = sv;
            wsum   += sv;

            if (lane == wl) {
#pragma unroll
                for (int j = 0; j < 8; j++) if (j == wj) kv[j] = 0u;
            }
        }

        if (lane == 0) {
            float inv = SCALE / wsum;
            size_t half = (size_t)T * TOP_K;
#pragma unroll
            for (int r = 0; r < TOP_K; r++) {
                out[(size_t)t * TOP_K + r]        = (float)idxs[r];
                out[half + (size_t)t * TOP_K + r] = wts[r] * inv;
            }
        }
    }
}

// ---------------------------------------------------------------------------
extern "C" void kernel_launch(void* const* d_in, const int* in_sizes, int n_in,
                              void* d_out, int out_size)
{
    const float* x    = (const float*)d_in[0];   // [B,S,H] fp32
    const float* w    = (const float*)d_in[1];   // [E,H]   fp32
    const float* bias = (const float*)d_in[2];   // [E]     fp32
    float* out = (float*)d_out;

    const int E = in_sizes[2];                   // 256
    const int H = in_sizes[1] / E;               // 7168
    const int T = in_sizes[0] / H;               // 8192

    // 0) split prescaled weights into fp16x2 (4 float4 per thread)
    {
        int n4 = E * H / 4;
        split_w_kernel<<<(n4 + 1023) / 1024, 256>>>(w);
    }

    // 1) tensor-core GEMM -> g_logits (+ g_logits2 small-K partials)
    cudaFuncSetAttribute(moe_gemm_mma,
                         cudaFuncAttributeMaxDynamicSharedMemorySize, GEMM_SMEM);
    moe_gemm_mma<<<256, 256, GEMM_SMEM>>>(x);    // 128 big + 128 small CTAs

    // 2) grouped top-k (2 tokens per warp)
    dim3 topkGrid((T + 15) / 16);
    moe_topk_kernel<<<topkGrid, 256>>>(bias, out, T);
}

// round 16
// speedup vs baseline: 1.2129x; 1.0232x over previous
#include <cuda_runtime.h>
#include <cuda_fp16.h>
#include <math.h>
#include <float.h>
#include <stdint.h>

// ============================================================================
// DeepSeekV3 MoE Gate (sm_103a; PTX target compute_103 -> no tcgen05).
// GEMM via mma.sync.m16n8k16 fp16, fp16x2 split, 3 passes (hh, hm, mh),
// W prescaled x64 (single fp32 accumulator), periodic RN master flush.
// Split-K: 128 big tiles (K-chunks 0..98) + 128 small tiles (chunks 99..111)
// backfilling the 20 otherwise-idle SMs.
// R16: BIGC 100->99 (critical-path shave), topk reverted to 1 token/warp,
// split_w paired-float4 with uint4 stores.
// Output (float32): [ T*8 indices (as float) | T*8 weights ]
// ============================================================================

#define N_EXPERTS 256
#define TOPK_GRP  4
#define TOP_K     8
#define SCALE     2.5f
#define H_DIM     7168
#define MAX_T     8192
#define W_PRESCALE   64.0f
#define W_POSTSCALE  0.015625f   // 1/64

__device__ float g_logits [MAX_T * N_EXPERTS];                // big partials
__device__ float g_logits2[MAX_T * N_EXPERTS];                // small partials
__device__ __align__(16) __half g_wh[N_EXPERTS * H_DIM];      // fp16(64*w)
__device__ __align__(16) __half g_wm[N_EXPERTS * H_DIM];      // fp16(64*w - hi)

// ---------------------------------------------------------------------------
// helpers
// ---------------------------------------------------------------------------
__device__ __forceinline__ uint32_t smem_to_u32(const void* p) {
    uint32_t a;
    asm("{ .reg .u64 t; cvta.to.shared.u64 t, %1; cvt.u32.u64 %0, t; }"
        : "=r"(a) : "l"(p));
    return a;
}
__device__ __forceinline__ void cp16(uint32_t dst, const void* src) {
    asm volatile("cp.async.cg.shared.global [%0], [%1], 16;" :: "r"(dst), "l"(src));
}
#define CP_COMMIT() asm volatile("cp.async.commit_group;" ::: "memory")
#define CP_WAIT1()  asm volatile("cp.async.wait_group 1;" ::: "memory")

__device__ __forceinline__ void ldmatrix_x4(uint32_t* r, uint32_t addr) {
    asm volatile("ldmatrix.sync.aligned.m8n8.x4.shared.b16 {%0,%1,%2,%3}, [%4];"
                 : "=r"(r[0]), "=r"(r[1]), "=r"(r[2]), "=r"(r[3]) : "r"(addr));
}
__device__ __forceinline__ void mma_fp16(float* d, const uint32_t* a,
                                         uint32_t b0, uint32_t b1) {
    asm volatile(
        "mma.sync.aligned.m16n8k16.row.col.f32.f16.f16.f32 "
        "{%0,%1,%2,%3}, {%4,%5,%6,%7}, {%8,%9}, {%0,%1,%2,%3};"
        : "+f"(d[0]), "+f"(d[1]), "+f"(d[2]), "+f"(d[3])
        : "r"(a[0]), "r"(a[1]), "r"(a[2]), "r"(a[3]), "r"(b0), "r"(b1));
}

// split a float2 into 2 packed fp16x2 (hi, mid); low 16 bits = f.x
__device__ __forceinline__ void split2(float2 f, uint32_t& h, uint32_t& m) {
    __half2 hh = __floats2half2_rn(f.x, f.y);
    h = *reinterpret_cast<uint32_t*>(&hh);
    float2 hf = __half22float2(hh);
    __half2 mm2 = __floats2half2_rn(f.x - hf.x, f.y - hf.y);
    m = *reinterpret_cast<uint32_t*>(&mm2);
}

// monotone float <-> unsigned-comparable key (finite inputs map to key > 0)
__device__ __forceinline__ unsigned f2ord(float f) {
    unsigned u = __float_as_uint(f);
    return u ^ ((((int)u) >> 31) | 0x80000000u);
}
__device__ __forceinline__ float ord2f(unsigned k) {
    unsigned u = (k & 0x80000000u) ? (k ^ 0x80000000u) : ~k;
    return __uint_as_float(u);
}

// ---------------------------------------------------------------------------
// Kernel 0: split prescaled fp32 weights -> 2 fp16 tensors.
// Each thread: 2 adjacent float4 (32B read) -> one uint4 store to each output.
// ---------------------------------------------------------------------------
__global__ __launch_bounds__(256)
void split_w_kernel(const float* __restrict__ w)
{
    const int n8 = N_EXPERTS * H_DIM / 8;       // pairs of float4
    int i = blockIdx.x * 256 + threadIdx.x;
    if (i >= n8) return;
    float4 v0 = reinterpret_cast<const float4*>(w)[2 * i];
    float4 v1 = reinterpret_cast<const float4*>(w)[2 * i + 1];
    uint32_t h0, m0, h1, m1, h2, m2, h3, m3;
    split2(make_float2(v0.x * W_PRESCALE, v0.y * W_PRESCALE), h0, m0);
    split2(make_float2(v0.z * W_PRESCALE, v0.w * W_PRESCALE), h1, m1);
    split2(make_float2(v1.x * W_PRESCALE, v1.y * W_PRESCALE), h2, m2);
    split2(make_float2(v1.z * W_PRESCALE, v1.w * W_PRESCALE), h3, m3);
    reinterpret_cast<uint4*>(g_wh)[i] = make_uint4(h0, h1, h2, h3);
    reinterpret_cast<uint4*>(g_wm)[i] = make_uint4(m0, m1, m2, m3);
}

// ---------------------------------------------------------------------------
// Kernel 1: GEMM via mma.sync fp16x2, 3 passes, single accumulator + RN flush.
// CTA tile: 128 tokens x 128 experts, split in K:
//   bid 0..127  : big   segment, chunks [0, BIGC)
//   bid 128..255: small segment, chunks [BIGC, NCHUNK)
// BK=64. 3-stage cp.async pipeline. 1 CTA/SM. (Mainloop PROVEN — unchanged.)
// ---------------------------------------------------------------------------
#define BM        128
#define BN        128
#define BK        64
#define NCHUNK    (H_DIM / BK)          // 112
#define BIGC      99                    // big segment: chunks 0..98 (K=6336)
#define FLUSH_MASK 3                    // flush every 4 local chunks (K=256)
#define A_ROWB    288                   // 72 floats
#define A_BYTES   (128 * A_ROWB)        // 36864
#define B_ROWB    144
#define B_SPLIT_B (128 * B_ROWB)        // 18432
#define STAGE_B   (A_BYTES + 2 * B_SPLIT_B)  // 73728
#define GEMM_SMEM (3 * STAGE_B)              // 221184

__device__ __forceinline__ void load_stage(const float* __restrict__ x,
                                           int row0, int e0, int k0,
                                           uint32_t stage_base, int tid)
{
    // A: 128 rows x 64 fp32 (256B payload/row, stride 288B): 2048 cp16
#pragma unroll
    for (int l = 0; l < 8; l++) {
        int q = tid + 256 * l;             // 0..2047
        int row = q >> 4, seg = q & 15;
        const float* src = x + (size_t)(row0 + row) * H_DIM + k0 + seg * 4;
        cp16(stage_base + row * A_ROWB + seg * 16, src);
    }
    // B: 2 splits x 128 rows x 64 fp16 (128B payload/row, stride 144B): 2048 cp16
#pragma unroll
    for (int l = 0; l < 8; l++) {
        int q = tid + 256 * l;             // 0..2047
        int s = q >> 10;                   // split
        int r = q & 1023;
        int row = r >> 3, seg = r & 7;
        const __half* wp = s ? g_wm : g_wh;
        const __half* src = wp + (size_t)(e0 + row) * H_DIM + k0 + seg * 8;
        cp16(stage_base + A_BYTES + s * B_SPLIT_B + row * B_ROWB + seg * 16, src);
    }
}

__global__ __launch_bounds__(256, 1)
void moe_gemm_mma(const float* __restrict__ x)
{
    extern __shared__ char smem[];
    const uint32_t sbase = smem_to_u32(smem);
    const int tid  = threadIdx.x;
    const int lane = tid & 31;
    const int wid  = tid >> 5;
    const int wm   = wid & 3;              // warp row (m)
    const int wn   = wid >> 2;             // warp col (n)

    const int bid  = blockIdx.x;
    const bool big = bid < 128;
    const int tile = big ? bid : bid - 128;
    const int row0 = (tile >> 1) * BM;
    const int e0   = (tile & 1) * BN;
    const int c0   = big ? 0 : BIGC;       // first chunk (inclusive)
    const int cn   = big ? BIGC : NCHUNK;  // last chunk (exclusive)
    float* dst = big ? g_logits : g_logits2;

    float acc[2][8][4];                    // short-chain accumulators
    float master[2][8][4];                 // RN-summed masters
#pragma unroll
    for (int mt = 0; mt < 2; mt++)
#pragma unroll
        for (int nt = 0; nt < 8; nt++)
#pragma unroll
            for (int q = 0; q < 4; q++) { acc[mt][nt][q] = 0.0f; master[mt][nt][q] = 0.0f; }

    // prologue: stages c0, c0+1
    load_stage(x, row0, e0, c0 * BK,       sbase + 0 * STAGE_B, tid); CP_COMMIT();
    load_stage(x, row0, e0, (c0 + 1) * BK, sbase + 1 * STAGE_B, tid); CP_COMMIT();

    const int c2 = (lane & 3) * 2;         // k-pair base within 8

    for (int lc = 0; lc < cn - c0; ++lc) { // local chunk index
        const int c = c0 + lc;
        CP_WAIT1();
        __syncthreads();

        if (c + 2 < cn)
            load_stage(x, row0, e0, (c + 2) * BK, sbase + ((lc + 2) % 3) * STAGE_B, tid);
        CP_COMMIT();

        const int slot = lc % 3;
        const char* As = smem + slot * STAGE_B;
        const uint32_t Bs = sbase + slot * STAGE_B + A_BYTES;

#pragma unroll
        for (int kk = 0; kk < 4; kk++) {           // four k16 steps per BK=64
            // ---- A fragments: load fp32 pairs, split to fp16x2 ----
            uint32_t ah[2][4], am[2][4];
#pragma unroll
            for (int mt = 0; mt < 2; mt++) {
                int brow = wm * 32 + mt * 16 + (lane >> 2);
#pragma unroll
                for (int q = 0; q < 4; q++) {
                    int r   = brow + (q & 1) * 8;
                    int col = kk * 16 + c2 + (q >> 1) * 8;
                    float2 f = *reinterpret_cast<const float2*>(As + r * A_ROWB + col * 4);
                    split2(f, ah[mt][q], am[mt][q]);
                }
            }
            // ---- 3 passes: s=0 -> ah*bh + am*bh ; s=1 -> ah*bm ----
#pragma unroll
            for (int s = 0; s < 2; s++) {
                uint32_t b[4][4];
#pragma unroll
                for (int p = 0; p < 4; p++) {
                    int row = wn * 64 + p * 16 + (lane & 7) + ((lane >> 4) & 1) * 8;
                    uint32_t addr = Bs + s * B_SPLIT_B + row * B_ROWB
                                  + kk * 32 + ((lane >> 3) & 1) * 16;
                    ldmatrix_x4(b[p], addr);
                }
#pragma unroll
                for (int mt = 0; mt < 2; mt++)
#pragma unroll
                    for (int nt = 0; nt < 8; nt++) {
                        int p = nt >> 1, o = (nt & 1) * 2;
                        mma_fp16(acc[mt][nt], ah[mt], b[p][o], b[p][o + 1]);
                    }
                if (s == 0) {
#pragma unroll
                    for (int mt = 0; mt < 2; mt++)
#pragma unroll
                        for (int nt = 0; nt < 8; nt++) {
                            int p = nt >> 1, o = (nt & 1) * 2;
                            mma_fp16(acc[mt][nt], am[mt], b[p][o], b[p][o + 1]);
                        }
                }
            }
        }

        // ---- RN flush: keep tensor-core accumulation chains short ----
        if ((lc & FLUSH_MASK) == FLUSH_MASK) {
#pragma unroll
            for (int mt = 0; mt < 2; mt++)
#pragma unroll
                for (int nt = 0; nt < 8; nt++)
#pragma unroll
                    for (int q = 0; q < 4; q++) {
                        master[mt][nt][q] += acc[mt][nt][q];
                        acc[mt][nt][q] = 0.0f;
                    }
        }
    }

    // fold residual chunks (segment length not a multiple of 4)
#pragma unroll
    for (int mt = 0; mt < 2; mt++)
#pragma unroll
        for (int nt = 0; nt < 8; nt++)
#pragma unroll
            for (int q = 0; q < 4; q++) master[mt][nt][q] += acc[mt][nt][q];

    // epilogue: write partial logits (undo W prescale)
#pragma unroll
    for (int mt = 0; mt < 2; mt++) {
        int row = row0 + wm * 32 + mt * 16 + (lane >> 2);
#pragma unroll
        for (int nt = 0; nt < 8; nt++) {
            int col = e0 + wn * 64 + nt * 8 + c2;
            *reinterpret_cast<float2*>(&dst[(size_t)row * N_EXPERTS + col]) =
                make_float2(master[mt][nt][0] * W_POSTSCALE,
                            master[mt][nt][1] * W_POSTSCALE);
            *reinterpret_cast<float2*>(&dst[(size_t)(row + 8) * N_EXPERTS + col]) =
                make_float2(master[mt][nt][2] * W_POSTSCALE,
                            master[mt][nt][3] * W_POSTSCALE);
        }
    }
}

// ---------------------------------------------------------------------------
// Kernel 2: per-token grouped top-k. One warp per token (proven R13 version).
// Tie semantics preserved exactly: value desc, tie -> lowest expert index.
// ---------------------------------------------------------------------------
__global__ __launch_bounds__(256)
void moe_topk_kernel(const float* __restrict__ bias, float* __restrict__ out, int T)
{
    const unsigned FULL = 0xFFFFFFFFu;
    const int lane   = threadIdx.x & 31;
    const int warpId = threadIdx.x >> 5;
    const int t = blockIdx.x * 8 + warpId;
    if (t >= T) return;

    const float* lg  = &g_logits [(size_t)t * N_EXPERTS];
    const float* lg2 = &g_logits2[(size_t)t * N_EXPERTS];

    float s[8];
    unsigned k[8];                         // monotone keys of sb (all > 0)
#pragma unroll
    for (int j = 0; j < 8; j++) {
        int e = j * 32 + lane;
        float logit = lg[e] + lg2[e];      // fixed-order partial sum
        float sv = 1.0f / (1.0f + __expf(-logit));
        s[j] = sv;
        k[j] = f2ord(sv + bias[e]);
    }

    // per-group top-2 sum via REDUX (sum is tie-insensitive)
    float gs[8];
#pragma unroll
    for (int g = 0; g < 8; g++) {
        unsigned m1 = __reduce_max_sync(FULL, k[g]);
        unsigned bal = __ballot_sync(FULL, k[g] == m1);
        int leader = __ffs(bal) - 1;
        unsigned k2 = (lane == leader) ? 0u : k[g];
        unsigned m2 = __reduce_max_sync(FULL, k2);
        gs[g] = ord2f(m1) + ord2f(m2);
    }

    unsigned gmask = 0;
#pragma unroll
    for (int r = 0; r < TOPK_GRP; r++) {
        float best = -FLT_MAX; int bg = 0;
#pragma unroll
        for (int g = 0; g < 8; g++) {
            bool taken = (gmask >> g) & 1u;
            if (!taken && gs[g] > best) { best = gs[g]; bg = g; }
        }
        gmask |= (1u << bg);
    }

    // candidate keys: 0 = removed/inactive (all real keys > 0)
    unsigned kv[8];
#pragma unroll
    for (int j = 0; j < 8; j++)
        kv[j] = ((gmask >> j) & 1u) ? k[j] : 0u;

    float wts[TOP_K];
    int   idxs[TOP_K];
    float wsum = 0.0f;
#pragma unroll
    for (int r = 0; r < TOP_K; r++) {
        // lane-local max key
        unsigned kb = kv[0];
#pragma unroll
        for (int j = 1; j < 8; j++) kb = kb > kv[j] ? kb : kv[j];
        // warp max key
        unsigned m = __reduce_max_sync(FULL, kb);
        // lowest expert index holding key m (descending j -> final = smallest j)
        int myidx = 0x7FFFFFFF;
#pragma unroll
        for (int j = 7; j >= 0; j--)
            if (kv[j] == m) myidx = j * 32 + lane;
        int widx = __reduce_min_sync(FULL, myidx);

        int wl = widx & 31;
        int wj = widx >> 5;
        float sv_local = 0.0f;
#pragma unroll
        for (int j = 0; j < 8; j++) if (j == wj) sv_local = s[j];
        float sv = __shfl_sync(FULL, sv_local, wl);

        idxs[r] = widx;
        wts[r]  = sv;
        wsum   += sv;

        if (lane == wl) {
#pragma unroll
            for (int j = 0; j < 8; j++) if (j == wj) kv[j] = 0u;
        }
    }

    if (lane == 0) {
        float inv = SCALE / wsum;
        size_t half = (size_t)T * TOP_K;
#pragma unroll
        for (int r = 0; r < TOP_K; r++) {
            out[(size_t)t * TOP_K + r]        = (float)idxs[r];
            out[half + (size_t)t * TOP_K + r] = wts[r] * inv;
        }
    }
}

// ---------------------------------------------------------------------------
extern "C" void kernel_launch(void* const* d_in, const int* in_sizes, int n_in,
                              void* d_out, int out_size)
{
    const float* x    = (const float*)d_in[0];   // [B,S,H] fp32
    const float* w    = (const float*)d_in[1];   // [E,H]   fp32
    const float* bias = (const float*)d_in[2];   // [E]     fp32
    float* out = (float*)d_out;

    const int E = in_sizes[2];                   // 256
    const int H = in_sizes[1] / E;               // 7168
    const int T = in_sizes[0] / H;               // 8192

    // 0) split prescaled weights into fp16x2 (2 adjacent float4 per thread)
    {
        int n8 = E * H / 8;
        split_w_kernel<<<(n8 + 255) / 256, 256>>>(w);
    }

    // 1) tensor-core GEMM -> g_logits (+ g_logits2 small-K partials)
    cudaFuncSetAttribute(moe_gemm_mma,
                         cudaFuncAttributeMaxDynamicSharedMemorySize, GEMM_SMEM);
    moe_gemm_mma<<<256, 256, GEMM_SMEM>>>(x);    // 128 big + 128 small CTAs

    // 2) grouped top-k (1 token per warp)
    dim3 topkGrid((T + 7) / 8);
    moe_topk_kernel<<<topkGrid, 256>>>(bias, out, T);
}

// round 17
// speedup vs baseline: 1.2323x; 1.0160x over previous
#include <cuda_runtime.h>
#include <cuda_fp16.h>
#include <math.h>
#include <float.h>
#include <stdint.h>

// ============================================================================
// DeepSeekV3 MoE Gate (sm_103a; PTX target compute_103 -> no tcgen05).
// GEMM via mma.sync.m16n8k16 fp16, fp16x2 split, 3 passes (hh, hm, mh),
// W prescaled x64 (single fp32 accumulator), periodic RN master flush.
// Split-K: 128 big tiles (K-chunks 0..98) + 128 small tiles (chunks 99..111)
// backfilling the 20 otherwise-idle SMs. (GEMM + split_w frozen from R16.)
// R17: topk quad-per-lane remap — float4 loads, octet-local group top-2.
// Output (float32): [ T*8 indices (as float) | T*8 weights ]
// ============================================================================

#define N_EXPERTS 256
#define TOPK_GRP  4
#define TOP_K     8
#define SCALE     2.5f
#define H_DIM     7168
#define MAX_T     8192
#define W_PRESCALE   64.0f
#define W_POSTSCALE  0.015625f   // 1/64

__device__ __align__(16) float g_logits [MAX_T * N_EXPERTS];  // big partials
__device__ __align__(16) float g_logits2[MAX_T * N_EXPERTS];  // small partials
__device__ __align__(16) __half g_wh[N_EXPERTS * H_DIM];      // fp16(64*w)
__device__ __align__(16) __half g_wm[N_EXPERTS * H_DIM];      // fp16(64*w - hi)

// ---------------------------------------------------------------------------
// helpers
// ---------------------------------------------------------------------------
__device__ __forceinline__ uint32_t smem_to_u32(const void* p) {
    uint32_t a;
    asm("{ .reg .u64 t; cvta.to.shared.u64 t, %1; cvt.u32.u64 %0, t; }"
        : "=r"(a) : "l"(p));
    return a;
}
__device__ __forceinline__ void cp16(uint32_t dst, const void* src) {
    asm volatile("cp.async.cg.shared.global [%0], [%1], 16;" :: "r"(dst), "l"(src));
}
#define CP_COMMIT() asm volatile("cp.async.commit_group;" ::: "memory")
#define CP_WAIT1()  asm volatile("cp.async.wait_group 1;" ::: "memory")

__device__ __forceinline__ void ldmatrix_x4(uint32_t* r, uint32_t addr) {
    asm volatile("ldmatrix.sync.aligned.m8n8.x4.shared.b16 {%0,%1,%2,%3}, [%4];"
                 : "=r"(r[0]), "=r"(r[1]), "=r"(r[2]), "=r"(r[3]) : "r"(addr));
}
__device__ __forceinline__ void mma_fp16(float* d, const uint32_t* a,
                                         uint32_t b0, uint32_t b1) {
    asm volatile(
        "mma.sync.aligned.m16n8k16.row.col.f32.f16.f16.f32 "
        "{%0,%1,%2,%3}, {%4,%5,%6,%7}, {%8,%9}, {%0,%1,%2,%3};"
        : "+f"(d[0]), "+f"(d[1]), "+f"(d[2]), "+f"(d[3])
        : "r"(a[0]), "r"(a[1]), "r"(a[2]), "r"(a[3]), "r"(b0), "r"(b1));
}

// split a float2 into 2 packed fp16x2 (hi, mid); low 16 bits = f.x
__device__ __forceinline__ void split2(float2 f, uint32_t& h, uint32_t& m) {
    __half2 hh = __floats2half2_rn(f.x, f.y);
    h = *reinterpret_cast<uint32_t*>(&hh);
    float2 hf = __half22float2(hh);
    __half2 mm2 = __floats2half2_rn(f.x - hf.x, f.y - hf.y);
    m = *reinterpret_cast<uint32_t*>(&mm2);
}

// monotone float <-> unsigned-comparable key (finite inputs map to key > 0)
__device__ __forceinline__ unsigned f2ord(float f) {
    unsigned u = __float_as_uint(f);
    return u ^ ((((int)u) >> 31) | 0x80000000u);
}

// ---------------------------------------------------------------------------
// Kernel 0: split prescaled fp32 weights -> 2 fp16 tensors.
// Each thread: 2 adjacent float4 (32B read) -> one uint4 store to each output.
// ---------------------------------------------------------------------------
__global__ __launch_bounds__(256)
void split_w_kernel(const float* __restrict__ w)
{
    const int n8 = N_EXPERTS * H_DIM / 8;       // pairs of float4
    int i = blockIdx.x * 256 + threadIdx.x;
    if (i >= n8) return;
    float4 v0 = reinterpret_cast<const float4*>(w)[2 * i];
    float4 v1 = reinterpret_cast<const float4*>(w)[2 * i + 1];
    uint32_t h0, m0, h1, m1, h2, m2, h3, m3;
    split2(make_float2(v0.x * W_PRESCALE, v0.y * W_PRESCALE), h0, m0);
    split2(make_float2(v0.z * W_PRESCALE, v0.w * W_PRESCALE), h1, m1);
    split2(make_float2(v1.x * W_PRESCALE, v1.y * W_PRESCALE), h2, m2);
    split2(make_float2(v1.z * W_PRESCALE, v1.w * W_PRESCALE), h3, m3);
    reinterpret_cast<uint4*>(g_wh)[i] = make_uint4(h0, h1, h2, h3);
    reinterpret_cast<uint4*>(g_wm)[i] = make_uint4(m0, m1, m2, m3);
}

// ---------------------------------------------------------------------------
// Kernel 1: GEMM via mma.sync fp16x2, 3 passes, single accumulator + RN flush.
// CTA tile: 128 tokens x 128 experts, split in K:
//   bid 0..127  : big   segment, chunks [0, BIGC)
//   bid 128..255: small segment, chunks [BIGC, NCHUNK)
// BK=64. 3-stage cp.async pipeline. 1 CTA/SM. (PROVEN — do not modify.)
// ---------------------------------------------------------------------------
#define BM        128
#define BN        128
#define BK        64
#define NCHUNK    (H_DIM / BK)          // 112
#define BIGC      99                    // big segment: chunks 0..98 (K=6336)
#define FLUSH_MASK 3                    // flush every 4 local chunks (K=256)
#define A_ROWB    288                   // 72 floats
#define A_BYTES   (128 * A_ROWB)        // 36864
#define B_ROWB    144
#define B_SPLIT_B (128 * B_ROWB)        // 18432
#define STAGE_B   (A_BYTES + 2 * B_SPLIT_B)  // 73728
#define GEMM_SMEM (3 * STAGE_B)              // 221184

__device__ __forceinline__ void load_stage(const float* __restrict__ x,
                                           int row0, int e0, int k0,
                                           uint32_t stage_base, int tid)
{
    // A: 128 rows x 64 fp32 (256B payload/row, stride 288B): 2048 cp16
#pragma unroll
    for (int l = 0; l < 8; l++) {
        int q = tid + 256 * l;             // 0..2047
        int row = q >> 4, seg = q & 15;
        const float* src = x + (size_t)(row0 + row) * H_DIM + k0 + seg * 4;
        cp16(stage_base + row * A_ROWB + seg * 16, src);
    }
    // B: 2 splits x 128 rows x 64 fp16 (128B payload/row, stride 144B): 2048 cp16
#pragma unroll
    for (int l = 0; l < 8; l++) {
        int q = tid + 256 * l;             // 0..2047
        int s = q >> 10;                   // split
        int r = q & 1023;
        int row = r >> 3, seg = r & 7;
        const __half* wp = s ? g_wm : g_wh;
        const __half* src = wp + (size_t)(e0 + row) * H_DIM + k0 + seg * 8;
        cp16(stage_base + A_BYTES + s * B_SPLIT_B + row * B_ROWB + seg * 16, src);
    }
}

__global__ __launch_bounds__(256, 1)
void moe_gemm_mma(const float* __restrict__ x)
{
    extern __shared__ char smem[];
    const uint32_t sbase = smem_to_u32(smem);
    const int tid  = threadIdx.x;
    const int lane = tid & 31;
    const int wid  = tid >> 5;
    const int wm   = wid & 3;              // warp row (m)
    const int wn   = wid >> 2;             // warp col (n)

    const int bid  = blockIdx.x;
    const bool big = bid < 128;
    const int tile = big ? bid : bid - 128;
    const int row0 = (tile >> 1) * BM;
    const int e0   = (tile & 1) * BN;
    const int c0   = big ? 0 : BIGC;       // first chunk (inclusive)
    const int cn   = big ? BIGC : NCHUNK;  // last chunk (exclusive)
    float* dst = big ? g_logits : g_logits2;

    float acc[2][8][4];                    // short-chain accumulators
    float master[2][8][4];                 // RN-summed masters
#pragma unroll
    for (int mt = 0; mt < 2; mt++)
#pragma unroll
        for (int nt = 0; nt < 8; nt++)
#pragma unroll
            for (int q = 0; q < 4; q++) { acc[mt][nt][q] = 0.0f; master[mt][nt][q] = 0.0f; }

    // prologue: stages c0, c0+1
    load_stage(x, row0, e0, c0 * BK,       sbase + 0 * STAGE_B, tid); CP_COMMIT();
    load_stage(x, row0, e0, (c0 + 1) * BK, sbase + 1 * STAGE_B, tid); CP_COMMIT();

    const int c2 = (lane & 3) * 2;         // k-pair base within 8

    for (int lc = 0; lc < cn - c0; ++lc) { // local chunk index
        const int c = c0 + lc;
        CP_WAIT1();
        __syncthreads();

        if (c + 2 < cn)
            load_stage(x, row0, e0, (c + 2) * BK, sbase + ((lc + 2) % 3) * STAGE_B, tid);
        CP_COMMIT();

        const int slot = lc % 3;
        const char* As = smem + slot * STAGE_B;
        const uint32_t Bs = sbase + slot * STAGE_B + A_BYTES;

#pragma unroll
        for (int kk = 0; kk < 4; kk++) {           // four k16 steps per BK=64
            // ---- A fragments: load fp32 pairs, split to fp16x2 ----
            uint32_t ah[2][4], am[2][4];
#pragma unroll
            for (int mt = 0; mt < 2; mt++) {
                int brow = wm * 32 + mt * 16 + (lane >> 2);
#pragma unroll
                for (int q = 0; q < 4; q++) {
                    int r   = brow + (q & 1) * 8;
                    int col = kk * 16 + c2 + (q >> 1) * 8;
                    float2 f = *reinterpret_cast<const float2*>(As + r * A_ROWB + col * 4);
                    split2(f, ah[mt][q], am[mt][q]);
                }
            }
            // ---- 3 passes: s=0 -> ah*bh + am*bh ; s=1 -> ah*bm ----
#pragma unroll
            for (int s = 0; s < 2; s++) {
                uint32_t b[4][4];
#pragma unroll
                for (int p = 0; p < 4; p++) {
                    int row = wn * 64 + p * 16 + (lane & 7) + ((lane >> 4) & 1) * 8;
                    uint32_t addr = Bs + s * B_SPLIT_B + row * B_ROWB
                                  + kk * 32 + ((lane >> 3) & 1) * 16;
                    ldmatrix_x4(b[p], addr);
                }
#pragma unroll
                for (int mt = 0; mt < 2; mt++)
#pragma unroll
                    for (int nt = 0; nt < 8; nt++) {
                        int p = nt >> 1, o = (nt & 1) * 2;
                        mma_fp16(acc[mt][nt], ah[mt], b[p][o], b[p][o + 1]);
                    }
                if (s == 0) {
#pragma unroll
                    for (int mt = 0; mt < 2; mt++)
#pragma unroll
                        for (int nt = 0; nt < 8; nt++) {
                            int p = nt >> 1, o = (nt & 1) * 2;
                            mma_fp16(acc[mt][nt], am[mt], b[p][o], b[p][o + 1]);
                        }
                }
            }
        }

        // ---- RN flush: keep tensor-core accumulation chains short ----
        if ((lc & FLUSH_MASK) == FLUSH_MASK) {
#pragma unroll
            for (int mt = 0; mt < 2; mt++)
#pragma unroll
                for (int nt = 0; nt < 8; nt++)
#pragma unroll
                    for (int q = 0; q < 4; q++) {
                        master[mt][nt][q] += acc[mt][nt][q];
                        acc[mt][nt][q] = 0.0f;
                    }
        }
    }

    // fold residual chunks (segment length not a multiple of 4)
#pragma unroll
    for (int mt = 0; mt < 2; mt++)
#pragma unroll
        for (int nt = 0; nt < 8; nt++)
#pragma unroll
            for (int q = 0; q < 4; q++) master[mt][nt][q] += acc[mt][nt][q];

    // epilogue: write partial logits (undo W prescale)
#pragma unroll
    for (int mt = 0; mt < 2; mt++) {
        int row = row0 + wm * 32 + mt * 16 + (lane >> 2);
#pragma unroll
        for (int nt = 0; nt < 8; nt++) {
            int col = e0 + wn * 64 + nt * 8 + c2;
            *reinterpret_cast<float2*>(&dst[(size_t)row * N_EXPERTS + col]) =
                make_float2(master[mt][nt][0] * W_POSTSCALE,
                            master[mt][nt][1] * W_POSTSCALE);
            *reinterpret_cast<float2*>(&dst[(size_t)(row + 8) * N_EXPERTS + col]) =
                make_float2(master[mt][nt][2] * W_POSTSCALE,
                            master[mt][nt][3] * W_POSTSCALE);
        }
    }
}

// ---------------------------------------------------------------------------
// Kernel 2: per-token grouped top-k. One warp per token.
// R17 quad-per-lane: lane l holds experts {4l..4l+3} and {128+4l..128+4l+3}.
// Group g lives entirely in lane-octet (g&3): octet-local top-2 butterfly.
// Tie semantics preserved exactly: value desc, tie -> lowest expert index.
// ---------------------------------------------------------------------------
__global__ __launch_bounds__(256)
void moe_topk_kernel(const float* __restrict__ bias, float* __restrict__ out, int T)
{
    const unsigned FULL = 0xFFFFFFFFu;
    const int lane   = threadIdx.x & 31;
    const int warpId = threadIdx.x >> 5;
    const int t = blockIdx.x * 8 + warpId;
    if (t >= T) return;

    const float4* lgv  = reinterpret_cast<const float4*>(&g_logits [(size_t)t * N_EXPERTS]);
    const float4* lgv2 = reinterpret_cast<const float4*>(&g_logits2[(size_t)t * N_EXPERTS]);
    const float4* bv   = reinterpret_cast<const float4*>(bias);

    // quad 0: experts 4l..4l+3 (group lane>>3); quad 1: 128+4l.. (group 4+(lane>>3))
    float4 a0 = lgv[lane],      a1 = lgv[32 + lane];
    float4 b0 = lgv2[lane],     b1 = lgv2[32 + lane];
    float4 c0 = bv[lane],       c1 = bv[32 + lane];

    float s[8], sb[8];
    {
        float lg0[8] = {a0.x + b0.x, a0.y + b0.y, a0.z + b0.z, a0.w + b0.w,
                        a1.x + b1.x, a1.y + b1.y, a1.z + b1.z, a1.w + b1.w};
        float bb[8]  = {c0.x, c0.y, c0.z, c0.w, c1.x, c1.y, c1.z, c1.w};
#pragma unroll
        for (int i = 0; i < 8; i++) {
            float sv = 1.0f / (1.0f + __expf(-lg0[i]));
            s[i]  = sv;
            sb[i] = sv + bb[i];
        }
    }
    unsigned k[8];
#pragma unroll
    for (int i = 0; i < 8; i++) k[i] = f2ord(sb[i]);

    // lane-local top-2 over each quad (duplicate-safe)
    float m1a, m2a, m1b, m2b;
    {
        float p1 = fmaxf(sb[0], sb[1]), p2 = fminf(sb[0], sb[1]);
        float p3 = fmaxf(sb[2], sb[3]), p4 = fminf(sb[2], sb[3]);
        m1a = fmaxf(p1, p3);
        m2a = fmaxf(fminf(p1, p3), fmaxf(p2, p4));
        float q1 = fmaxf(sb[4], sb[5]), q2 = fminf(sb[4], sb[5]);
        float q3 = fmaxf(sb[6], sb[7]), q4 = fminf(sb[6], sb[7]);
        m1b = fmaxf(q1, q3);
        m2b = fmaxf(fminf(q1, q3), fmaxf(q2, q4));
    }
    // octet butterfly merge (offsets 1,2,4 stay within the 8-lane octet)
#pragma unroll
    for (int off = 1; off <= 4; off <<= 1) {
        float o1a = __shfl_xor_sync(FULL, m1a, off);
        float o2a = __shfl_xor_sync(FULL, m2a, off);
        float n1a = fmaxf(m1a, o1a);
        m2a = fmaxf(fminf(m1a, o1a), fmaxf(m2a, o2a));
        m1a = n1a;
        float o1b = __shfl_xor_sync(FULL, m1b, off);
        float o2b = __shfl_xor_sync(FULL, m2b, off);
        float n1b = fmaxf(m1b, o1b);
        m2b = fmaxf(fminf(m1b, o1b), fmaxf(m2b, o2b));
        m1b = n1b;
    }
    float gs0 = m1a + m2a;     // group (lane>>3), known to whole octet
    float gs1 = m1b + m2b;     // group 4+(lane>>3)

    // gather all 8 group scores (source lane g*8 is inside octet g)
    float gs[8];
#pragma unroll
    for (int g = 0; g < 4; g++) {
        gs[g]     = __shfl_sync(FULL, gs0, g * 8);
        gs[4 + g] = __shfl_sync(FULL, gs1, g * 8);
    }

    unsigned gmask = 0;
#pragma unroll
    for (int r = 0; r < TOPK_GRP; r++) {
        float best = -FLT_MAX; int bg = 0;
#pragma unroll
        for (int g = 0; g < 8; g++) {
            bool taken = (gmask >> g) & 1u;
            if (!taken && gs[g] > best) { best = gs[g]; bg = g; }
        }
        gmask |= (1u << bg);
    }

    // candidate keys: 0 = removed/inactive (all real keys > 0)
    const bool act0 = (gmask >> (lane >> 3)) & 1u;        // quad 0's group
    const bool act1 = (gmask >> (4 + (lane >> 3))) & 1u;  // quad 1's group
    unsigned kv[8];
#pragma unroll
    for (int i = 0; i < 4; i++) kv[i]     = act0 ? k[i]     : 0u;
#pragma unroll
    for (int i = 0; i < 4; i++) kv[4 + i] = act1 ? k[4 + i] : 0u;

    float wts[TOP_K];
    int   idxs[TOP_K];
    float wsum = 0.0f;
#pragma unroll
    for (int r = 0; r < TOP_K; r++) {
        // lane-local max key
        unsigned kb = kv[0];
#pragma unroll
        for (int i = 1; i < 8; i++) kb = kb > kv[i] ? kb : kv[i];
        // warp max key
        unsigned m = __reduce_max_sync(FULL, kb);
        // lowest expert index holding key m: scan this lane's experts in
        // DESCENDING global-index order so final assignment = smallest.
        int myidx = 0x7FFFFFFF;
#pragma unroll
        for (int i = 3; i >= 0; i--)               // quad 1: 128+4l+i (high)
            if (kv[4 + i] == m) myidx = 128 + 4 * lane + i;
#pragma unroll
        for (int i = 3; i >= 0; i--)               // quad 0: 4l+i (low)
            if (kv[i] == m) myidx = 4 * lane + i;
        int widx = __reduce_min_sync(FULL, myidx);

        // winner location: lane and slot
        int hi = widx >> 7;                        // 0 or 1
        int wl = (widx & 127) >> 2;
        int ws = (widx & 3) + hi * 4;
        float sv_local = 0.0f;
#pragma unroll
        for (int i = 0; i < 8; i++) if (i == ws) sv_local = s[i];
        float sv = __shfl_sync(FULL, sv_local, wl);

        idxs[r] = widx;
        wts[r]  = sv;
        wsum   += sv;

        if (lane == wl) {
#pragma unroll
            for (int i = 0; i < 8; i++) if (i == ws) kv[i] = 0u;
        }
    }

    if (lane == 0) {
        float inv = SCALE / wsum;
        size_t half = (size_t)T * TOP_K;
#pragma unroll
        for (int r = 0; r < TOP_K; r++) {
            out[(size_t)t * TOP_K + r]        = (float)idxs[r];
            out[half + (size_t)t * TOP_K + r] = wts[r] * inv;
        }
    }
}

// ---------------------------------------------------------------------------
extern "C" void kernel_launch(void* const* d_in, const int* in_sizes, int n_in,
                              void* d_out, int out_size)
{
    const float* x    = (const float*)d_in[0];   // [B,S,H] fp32
    const float* w    = (const float*)d_in[1];   // [E,H]   fp32
    const float* bias = (const float*)d_in[2];   // [E]     fp32
    float* out = (float*)d_out;

    const int E = in_sizes[2];                   // 256
    const int H = in_sizes[1] / E;               // 7168
    const int T = in_sizes[0] / H;               // 8192

    // 0) split prescaled weights into fp16x2 (2 adjacent float4 per thread)
    {
        int n8 = E * H / 8;
        split_w_kernel<<<(n8 + 255) / 256, 256>>>(w);
    }

    // 1) tensor-core GEMM -> g_logits (+ g_logits2 small-K partials)
    cudaFuncSetAttribute(moe_gemm_mma,
                         cudaFuncAttributeMaxDynamicSharedMemorySize, GEMM_SMEM);
    moe_gemm_mma<<<256, 256, GEMM_SMEM>>>(x);    // 128 big + 128 small CTAs

    // 2) grouped top-k (1 token per warp, quad-per-lane)
    dim3 topkGrid((T + 7) / 8);
    moe_topk_kernel<<<topkGrid, 256>>>(bias, out, T);
}